// round 13
// baseline (speedup 1.0000x reference)
#include <cuda_runtime.h>
#include <cuda_bf16.h>
#include <cstddef>
#include <cstdint>

// B=8, C=1024, Ci=512, N=T*H*W=2048
constexpr int Bn   = 8;
constexpr int C    = 1024;
constexpr int Ci   = 512;
constexpr int NSP  = 2048;

constexpr int TPB4     = 128;   // 4 warps, warp tile 64x64 (proj/ygemm/final)
constexpr int TPB8     = 256;   // 8 warps, warp tile 64x32 (scores)
constexpr int SOFT_TPB = 256;

// smem tile geometry (bf16 elements)
constexpr int ANS2     = 40;             // natural combined hi|lo row stride
constexpr int NAT_B    = 128 * ANS2 * 2; // 10240 bytes per natural tile
constexpr int NAT_STEP = 32 * ANS2 * 2;  // row+32 dst step
constexpr int KMS      = 136;            // k-major plane row stride
constexpr int KM_PLANE = 16 * KMS * 2;   // 4352 bytes per plane
constexpr int KM_B     = 2 * KM_PLANE;   // 8704 bytes (hi+lo)
constexpr int KM8      = 8 * KMS * 2;    // k+8 dst step

// stage strides / total dynamic smem
constexpr int SOFF_PROJ  = NAT_B + KM_B;   // 18944
constexpr int SOFF_SCORE = KM_B + KM_B;    // 17408
constexpr int SOFF_YG    = NAT_B + NAT_B;  // 20480
constexpr int SM_PROJ  = 4 * SOFF_PROJ;
constexpr int SM_SCORE = 4 * SOFF_SCORE;
constexpr int SM_YG    = 4 * SOFF_YG;

// ---------------------------------------------------------------------------
// gmem scratch
// ---------------------------------------------------------------------------
__device__ float d_f[(size_t)Bn * NSP * NSP];
__device__ __align__(16) unsigned short x_h[(size_t)Bn * C * NSP],  x_l[(size_t)Bn * C * NSP];
__device__ __align__(16) unsigned short w3_h[1536 * 1024],          w3_l[1536 * 1024];
__device__ __align__(16) unsigned short ww_h[1024 * 512],           ww_l[1024 * 512];
__device__ __align__(16) unsigned short g_h[(size_t)Bn * Ci * NSP], g_l[(size_t)Bn * Ci * NSP];
__device__ __align__(16) unsigned short th_h[(size_t)Bn * Ci * NSP], th_l[(size_t)Bn * Ci * NSP];
__device__ __align__(16) unsigned short ph_h[(size_t)Bn * Ci * NSP], ph_l[(size_t)Bn * Ci * NSP];
__device__ __align__(16) unsigned short P_h[(size_t)Bn * NSP * NSP], P_l[(size_t)Bn * NSP * NSP];
__device__ __align__(16) unsigned short y_h[(size_t)Bn * Ci * NSP],  y_l[(size_t)Bn * Ci * NSP];

// ---------------------------------------------------------------------------
// helpers
// ---------------------------------------------------------------------------
__device__ __forceinline__ unsigned smaddr(const void* p) {
    return (unsigned)__cvta_generic_to_shared(p);
}
__device__ __forceinline__ void cpa16s(unsigned daddr, const void* src) {
    asm volatile("cp.async.cg.shared.global [%0], [%1], 16;"
                 :: "r"(daddr), "l"(src) : "memory");
}
__device__ __forceinline__ void cp_commit() { asm volatile("cp.async.commit_group;" ::: "memory"); }
template<int N> __device__ __forceinline__ void cp_wait() {
    asm volatile("cp.async.wait_group %0;" :: "n"(N) : "memory");
}
__device__ __forceinline__ void ldsm4a(unsigned addr, unsigned& r0, unsigned& r1,
                                       unsigned& r2, unsigned& r3) {
    asm volatile("ldmatrix.sync.aligned.m8n8.x4.shared.b16 {%0,%1,%2,%3}, [%4];"
                 : "=r"(r0), "=r"(r1), "=r"(r2), "=r"(r3) : "r"(addr));
}
__device__ __forceinline__ void ldsm4ta(unsigned addr, unsigned& r0, unsigned& r1,
                                        unsigned& r2, unsigned& r3) {
    asm volatile("ldmatrix.sync.aligned.m8n8.x4.trans.shared.b16 {%0,%1,%2,%3}, [%4];"
                 : "=r"(r0), "=r"(r1), "=r"(r2), "=r"(r3) : "r"(addr));
}
__device__ __forceinline__ void mma_bf(float* c, const unsigned* a, unsigned b0, unsigned b1) {
    asm volatile(
        "mma.sync.aligned.m16n8k16.row.col.f32.bf16.bf16.f32 "
        "{%0,%1,%2,%3}, {%4,%5,%6,%7}, {%8,%9}, {%0,%1,%2,%3};"
        : "+f"(c[0]), "+f"(c[1]), "+f"(c[2]), "+f"(c[3])
        : "r"(a[0]), "r"(a[1]), "r"(a[2]), "r"(a[3]), "r"(b0), "r"(b1));
}
__device__ __forceinline__ void split1(float v, unsigned short& h, unsigned short& l) {
    __nv_bfloat16 hb = __float2bfloat16_rn(v);
    __nv_bfloat16 lb = __float2bfloat16_rn(v - __bfloat162float(hb));
    h = *reinterpret_cast<unsigned short*>(&hb);
    l = *reinterpret_cast<unsigned short*>(&lb);
}
__device__ __forceinline__ unsigned pack2(unsigned short a, unsigned short b) {
    return (unsigned)a | ((unsigned)b << 16);
}

// fragment offset builders (byte offsets within a stage's operand tile)
__device__ __forceinline__ void mk_aofs_nat(int lane, int wm, unsigned* o) {
    #pragma unroll
    for (int i = 0; i < 4; ++i)
        o[i] = (unsigned)(((wm + i * 16 + (lane & 15)) * ANS2 + ((lane >> 4) & 1) * 8) * 2);
}
__device__ __forceinline__ void mk_aofs_kmt(int lane, int wm, unsigned* o) {
    const int k = (lane & 7) + ((lane >> 3) & 1) * 8;
    #pragma unroll
    for (int i = 0; i < 4; ++i)
        o[i] = (unsigned)((k * KMS + wm + i * 16 + (lane >> 4) * 8) * 2);
}
template<int JT>
__device__ __forceinline__ void mk_bofs_kmt(int lane, int wn, unsigned* o) {
    const int k = (lane & 7) + ((lane >> 3) & 1) * 8;
    #pragma unroll
    for (int jj = 0; jj < JT; ++jj)
        o[jj] = (unsigned)((k * KMS + wn + jj * 16 + (lane >> 4) * 8) * 2);
}
template<int JT>
__device__ __forceinline__ void mk_bofs_nat(int lane, int wn, unsigned* o) {
    #pragma unroll
    for (int jj = 0; jj < JT; ++jj)
        o[jj] = (unsigned)(((wn + jj * 16 + ((lane >> 4) & 1) * 8 + (lane & 7)) * ANS2
                            + ((lane >> 3) & 1) * 8) * 2);
}

// 3xBF16 warp-tile compute for one k16 stage. JT = n16-tiles per warp (2 or 4).
// MMA issue order: per (jj,jr) the three split terms are each swept across all
// four i-tiles before the next term -> dependency distance 4 on every
// accumulator (HMMA lat/rt ~3), while per-accumulator term order (hh,hl,lh)
// is unchanged -> bit-identical results vs R12.
template<int JT, bool AKM, bool BKM>
__device__ __forceinline__ void comp_tile(unsigned ab, unsigned bb,
                                          const unsigned* aofs, const unsigned* bofs,
                                          float (&acc)[4][2 * JT][4]) {
    unsigned ah[4][4], al[4][4];
    #pragma unroll
    for (int i = 0; i < 4; ++i) {
        if (AKM) {
            unsigned r0, r1, r2, r3;
            ldsm4ta(ab + aofs[i], r0, r1, r2, r3);
            ah[i][0] = r0; ah[i][1] = r2; ah[i][2] = r1; ah[i][3] = r3;
            ldsm4ta(ab + KM_PLANE + aofs[i], r0, r1, r2, r3);
            al[i][0] = r0; al[i][1] = r2; al[i][2] = r1; al[i][3] = r3;
        } else {
            ldsm4a(ab + aofs[i],      ah[i][0], ah[i][1], ah[i][2], ah[i][3]);
            ldsm4a(ab + aofs[i] + 32, al[i][0], al[i][1], al[i][2], al[i][3]);
        }
    }
    #pragma unroll
    for (int jj = 0; jj < JT; ++jj) {
        unsigned bh[4], bl[4];
        if (BKM) {
            ldsm4ta(bb + bofs[jj],            bh[0], bh[1], bh[2], bh[3]);
            ldsm4ta(bb + KM_PLANE + bofs[jj], bl[0], bl[1], bl[2], bl[3]);
        } else {
            ldsm4a(bb + bofs[jj],      bh[0], bh[1], bh[2], bh[3]);
            ldsm4a(bb + bofs[jj] + 32, bl[0], bl[1], bl[2], bl[3]);
        }
        #pragma unroll
        for (int jr = 0; jr < 2; ++jr) {
            const int j = jj * 2 + jr;
            #pragma unroll
            for (int i = 0; i < 4; ++i)
                mma_bf(acc[i][j], ah[i], bh[jr*2], bh[jr*2+1]);
            #pragma unroll
            for (int i = 0; i < 4; ++i)
                mma_bf(acc[i][j], ah[i], bl[jr*2], bl[jr*2+1]);
            #pragma unroll
            for (int i = 0; i < 4; ++i)
                mma_bf(acc[i][j], al[i], bh[jr*2], bh[jr*2+1]);
        }
    }
}

#define ACC_INIT(acc, JN)                                    \
    float acc[4][JN][4];                                     \
    _Pragma("unroll") for (int i = 0; i < 4; ++i)            \
    _Pragma("unroll") for (int j = 0; j < JN; ++j)           \
    _Pragma("unroll") for (int q = 0; q < 4; ++q) acc[i][j][q] = 0.f;

#define PIPE_WAIT(kt, KT)                                    \
    if ((kt) + 2 < (KT)) cp_wait<2>();                       \
    else if ((kt) + 1 < (KT)) cp_wait<1>();                  \
    else cp_wait<0>();

// ---------------------------------------------------------------------------
// Pre-pass
// ---------------------------------------------------------------------------
__global__ void k_prep_w(const float* __restrict__ gw, const float* __restrict__ tw,
                         const float* __restrict__ pw, const float* __restrict__ Ww)
{
    const int idx = blockIdx.x * 256 + threadIdx.x;
    if (idx < 1536 * 1024) {
        const int r = idx >> 10, c = idx & 1023;
        float v = (r < 512) ? gw[r * 1024 + c]
                 : (r < 1024) ? tw[(r - 512) * 1024 + c]
                 : pw[(r - 1024) * 1024 + c];
        split1(v, w3_h[idx], w3_l[idx]);
    } else if (idx < 1536 * 1024 + 1024 * 512) {
        const int j = idx - 1536 * 1024;
        split1(Ww[j], ww_h[j], ww_l[j]);
    }
}
__global__ void k_prep_x(const float* __restrict__ x)
{
    const size_t i0 = ((size_t)blockIdx.x * 256 + threadIdx.x) * 2;
    const float2 v = *(const float2*)(x + i0);
    unsigned short h0, l0, h1, l1;
    split1(v.x, h0, l0); split1(v.y, h1, l1);
    *(unsigned*)(x_h + i0) = pack2(h0, h1);
    *(unsigned*)(x_l + i0) = pack2(l0, l1);
}

// ---------------------------------------------------------------------------
// Kernel 1: projections. A = W3 natural [o][c]; B = x k-major [c][n].
// 4 warps, 64x64 warp tile, NO mainloop unroll (reg budget).
// ---------------------------------------------------------------------------
__global__ __launch_bounds__(TPB4, 2)
void k_proj(const float* __restrict__ gb, const float* __restrict__ tbias,
            const float* __restrict__ pb)
{
    extern __shared__ char smdyn[];
    const unsigned sb = smaddr(smdyn);
    const int tid = threadIdx.x, lane = tid & 31, wid = tid >> 5;
    const int wm = (wid >> 1) * 64, wn = (wid & 1) * 64;
    const int n0 = blockIdx.x * 128, mt = blockIdx.y, b = blockIdx.z;
    const int mloc = (mt & 3) * 128;

    const unsigned short* Ah = w3_h + (size_t)mt * 128 * 1024;
    const unsigned short* Al = w3_l + (size_t)mt * 128 * 1024;
    const unsigned short* Xh = x_h + (size_t)b * C * NSP;
    const unsigned short* Xl = x_l + (size_t)b * C * NSP;

    const int row = tid >> 2, q = tid & 3;
    const unsigned short* nsrc = (q < 2 ? Ah : Al) + (size_t)row * 1024 + (q & 1) * 8;
    const unsigned nd = (unsigned)((row * ANS2 + (q >> 1) * 16 + (q & 1) * 8) * 2);
    const size_t n32 = (size_t)32 * 1024;
    const int k0 = tid >> 4, c8 = tid & 15;
    const unsigned short* ksH = Xh + (size_t)k0 * NSP + n0 + c8 * 8;
    const unsigned short* ksL = Xl + (size_t)k0 * NSP + n0 + c8 * 8;
    const unsigned kd = (unsigned)((k0 * KMS + c8 * 8) * 2) + NAT_B;
    const size_t k8 = (size_t)8 * NSP;
    const size_t kadv = (size_t)16 * NSP;

#define ISSUE_P(s) { const unsigned base = sb + (s) * SOFF_PROJ;                    \
        cpa16s(base + nd, nsrc);                      cpa16s(base + nd + NAT_STEP, nsrc + n32); \
        cpa16s(base + nd + 2 * NAT_STEP, nsrc + 2 * n32); cpa16s(base + nd + 3 * NAT_STEP, nsrc + 3 * n32); \
        cpa16s(base + kd, ksH);            cpa16s(base + kd + KM8, ksH + k8);       \
        cpa16s(base + kd + KM_PLANE, ksL); cpa16s(base + kd + KM_PLANE + KM8, ksL + k8); \
        cp_commit(); nsrc += 16; ksH += kadv; ksL += kadv; }

    unsigned aofs[4], bofs[4];
    mk_aofs_nat(lane, wm, aofs);
    mk_bofs_kmt<4>(lane, wn, bofs);

    ISSUE_P(0) ISSUE_P(1) ISSUE_P(2)
    ACC_INIT(acc, 8);
    const int KT = C / 16;
    for (int kt = 0; kt < KT; ++kt) {
        PIPE_WAIT(kt, KT);
        __syncthreads();
        if (kt + 3 < KT) ISSUE_P((kt + 3) & 3)
        const unsigned base = sb + (kt & 3) * SOFF_PROJ;
        comp_tile<4, false, true>(base, base + NAT_B, aofs, bofs, acc);
    }
#undef ISSUE_P

    const int gid = lane >> 2, tig = lane & 3;
    unsigned short *H, *L;
    const float* bias;
    if (mt < 4)      { H = g_h;  L = g_l;  bias = gb; }
    else if (mt < 8) { H = th_h; L = th_l; bias = tbias; }
    else             { H = ph_h; L = ph_l; bias = pb; }

    #pragma unroll
    for (int i = 0; i < 4; ++i) {
        const int ol = mloc + wm + i * 16 + gid;
        const float bv0 = bias[ol], bv1 = bias[ol + 8];
        #pragma unroll
        for (int j = 0; j < 8; ++j) {
            const int col = n0 + wn + j * 8 + tig * 2;
            const size_t a0 = ((size_t)b * Ci + ol) * NSP + col;
            const size_t a1 = ((size_t)b * Ci + ol + 8) * NSP + col;
            unsigned short h0, l0, h1, l1;
            split1(acc[i][j][0] + bv0, h0, l0); split1(acc[i][j][1] + bv0, h1, l1);
            *(unsigned*)(H + a0) = pack2(h0, h1); *(unsigned*)(L + a0) = pack2(l0, l1);
            split1(acc[i][j][2] + bv1, h0, l0); split1(acc[i][j][3] + bv1, h1, l1);
            *(unsigned*)(H + a1) = pack2(h0, h1); *(unsigned*)(L + a1) = pack2(l0, l1);
        }
    }
}

// ---------------------------------------------------------------------------
// Kernel 2: scores. Both operands k-major. 8 warps, 64x32 warp tile, unroll 4.
// ---------------------------------------------------------------------------
__global__ __launch_bounds__(TPB8, 2)
void k_scores()
{
    extern __shared__ char smdyn[];
    const unsigned sb = smaddr(smdyn);
    const int tid = threadIdx.x, lane = tid & 31, wid = tid >> 5;
    const int wm = (wid >> 2) * 64, wn = (wid & 3) * 32;
    const int m0 = blockIdx.x * 128, r0 = blockIdx.y * 128, b = blockIdx.z;

    const unsigned short* Th = th_h + (size_t)b * Ci * NSP;
    const unsigned short* Tl = th_l + (size_t)b * Ci * NSP;
    const unsigned short* Ph = ph_h + (size_t)b * Ci * NSP;
    const unsigned short* Pl = ph_l + (size_t)b * Ci * NSP;

    const int k0 = tid >> 4, c8 = tid & 15;
    const size_t kadv = (size_t)16 * NSP;
    const unsigned short* aH = Th + (size_t)k0 * NSP + r0 + c8 * 8;
    const unsigned short* aL = Tl + (size_t)k0 * NSP + r0 + c8 * 8;
    const unsigned short* bH = Ph + (size_t)k0 * NSP + m0 + c8 * 8;
    const unsigned short* bL = Pl + (size_t)k0 * NSP + m0 + c8 * 8;
    const unsigned ad = (unsigned)((k0 * KMS + c8 * 8) * 2);
    const unsigned bd = ad + KM_B;

#define ISSUE_S(s) { const unsigned base = sb + (s) * SOFF_SCORE;                   \
        cpa16s(base + ad, aH); cpa16s(base + ad + KM_PLANE, aL);                    \
        cpa16s(base + bd, bH); cpa16s(base + bd + KM_PLANE, bL);                    \
        cp_commit(); aH += kadv; aL += kadv; bH += kadv; bL += kadv; }

    unsigned aofs[4], bofs[2];
    mk_aofs_kmt(lane, wm, aofs);
    mk_bofs_kmt<2>(lane, wn, bofs);

    ISSUE_S(0) ISSUE_S(1) ISSUE_S(2)
    ACC_INIT(acc, 4);
    const int KT = Ci / 16;
    #pragma unroll 4
    for (int kt = 0; kt < KT; ++kt) {
        PIPE_WAIT(kt, KT);
        __syncthreads();
        if (kt + 3 < KT) ISSUE_S((kt + 3) & 3)
        const unsigned base = sb + (kt & 3) * SOFF_SCORE;
        comp_tile<2, true, true>(base, base + KM_B, aofs, bofs, acc);
    }
#undef ISSUE_S

    const int gid = lane >> 2, tig = lane & 3;
    float* fb = d_f + (size_t)b * NSP * NSP;
    #pragma unroll
    for (int i = 0; i < 4; ++i) {
        const int r = r0 + wm + i * 16 + gid;
        #pragma unroll
        for (int j = 0; j < 4; ++j) {
            const int col = m0 + wn + j * 8 + tig * 2;
            *(float2*)(fb + (size_t)r * NSP + col)       = *(float2*)&acc[i][j][0];
            *(float2*)(fb + (size_t)(r + 8) * NSP + col) = *(float2*)&acc[i][j][2];
        }
    }
}

// ---------------------------------------------------------------------------
// Kernel 3: softmax rows of d_f -> P hi/lo planes
// ---------------------------------------------------------------------------
__global__ __launch_bounds__(SOFT_TPB)
void k_softmax()
{
    const int tid = threadIdx.x;
    const size_t rowi = blockIdx.x;
    const float* row = d_f + rowi * NSP;

    float v[8];
    *(float4*)&v[0] = *(const float4*)(row + tid * 8);
    *(float4*)&v[4] = *(const float4*)(row + tid * 8 + 4);

    float m = v[0];
    #pragma unroll
    for (int i = 1; i < 8; i++) m = fmaxf(m, v[i]);
    #pragma unroll
    for (int o = 16; o; o >>= 1) m = fmaxf(m, __shfl_xor_sync(0xffffffffu, m, o));

    __shared__ float redm[8], reds[8];
    const int wid = tid >> 5, lane = tid & 31;
    if (lane == 0) redm[wid] = m;
    __syncthreads();
    m = redm[0];
    #pragma unroll
    for (int i = 1; i < 8; i++) m = fmaxf(m, redm[i]);

    float s = 0.f;
    #pragma unroll
    for (int i = 0; i < 8; i++) { v[i] = __expf(v[i] - m); s += v[i]; }
    #pragma unroll
    for (int o = 16; o; o >>= 1) s += __shfl_xor_sync(0xffffffffu, s, o);
    if (lane == 0) reds[wid] = s;
    __syncthreads();
    s = reds[0];
    #pragma unroll
    for (int i = 1; i < 8; i++) s += reds[i];

    const float inv = 1.0f / s;
    unsigned* Hp = (unsigned*)(P_h + rowi * NSP + tid * 8);
    unsigned* Lp = (unsigned*)(P_l + rowi * NSP + tid * 8);
    #pragma unroll
    for (int p = 0; p < 4; ++p) {
        unsigned short h0, l0, h1, l1;
        split1(v[2*p] * inv, h0, l0); split1(v[2*p+1] * inv, h1, l1);
        Hp[p] = pack2(h0, h1); Lp[p] = pack2(l0, l1);
    }
}

// ---------------------------------------------------------------------------
// Kernel 4: ygemm. Both operands natural. 4 warps, 64x64, NO unroll.
// ---------------------------------------------------------------------------
__global__ __launch_bounds__(TPB4, 2)
void k_ygemm()
{
    extern __shared__ char smdyn[];
    const unsigned sb = smaddr(smdyn);
    const int tid = threadIdx.x, lane = tid & 31, wid = tid >> 5;
    const int wm = (wid >> 1) * 64, wn = (wid & 1) * 64;
    const int n0 = blockIdx.x * 128, c0 = blockIdx.y * 128, b = blockIdx.z;

    const unsigned short* Gh = g_h + ((size_t)b * Ci + c0) * NSP;
    const unsigned short* Gl = g_l + ((size_t)b * Ci + c0) * NSP;
    const unsigned short* Qh = P_h + ((size_t)b * NSP + n0) * NSP;
    const unsigned short* Ql = P_l + ((size_t)b * NSP + n0) * NSP;

    const int row = tid >> 2, q = tid & 3;
    const size_t roff = (size_t)row * NSP + (q & 1) * 8;
    const unsigned short* asrc = (q < 2 ? Gh : Gl) + roff;
    const unsigned short* bsrc = (q < 2 ? Qh : Ql) + roff;
    const unsigned nd = (unsigned)((row * ANS2 + (q >> 1) * 16 + (q & 1) * 8) * 2);
    const size_t n32 = (size_t)32 * NSP;

#define ISSUE_Y(s) { const unsigned base = sb + (s) * SOFF_YG;                      \
        cpa16s(base + nd, asrc);                        cpa16s(base + nd + NAT_STEP, asrc + n32); \
        cpa16s(base + nd + 2 * NAT_STEP, asrc + 2 * n32); cpa16s(base + nd + 3 * NAT_STEP, asrc + 3 * n32); \
        cpa16s(base + NAT_B + nd, bsrc);                cpa16s(base + NAT_B + nd + NAT_STEP, bsrc + n32); \
        cpa16s(base + NAT_B + nd + 2 * NAT_STEP, bsrc + 2 * n32); \
        cpa16s(base + NAT_B + nd + 3 * NAT_STEP, bsrc + 3 * n32); \
        cp_commit(); asrc += 16; bsrc += 16; }

    unsigned aofs[4], bofs[4];
    mk_aofs_nat(lane, wm, aofs);
    mk_bofs_nat<4>(lane, wn, bofs);

    ISSUE_Y(0) ISSUE_Y(1) ISSUE_Y(2)
    ACC_INIT(acc, 8);
    const int KT = NSP / 16;
    for (int kt = 0; kt < KT; ++kt) {
        PIPE_WAIT(kt, KT);
        __syncthreads();
        if (kt + 3 < KT) ISSUE_Y((kt + 3) & 3)
        const unsigned base = sb + (kt & 3) * SOFF_YG;
        comp_tile<4, false, false>(base, base + NAT_B, aofs, bofs, acc);
    }
#undef ISSUE_Y

    const int gid = lane >> 2, tig = lane & 3;
    #pragma unroll
    for (int i = 0; i < 4; ++i) {
        const int r = c0 + wm + i * 16 + gid;
        #pragma unroll
        for (int j = 0; j < 8; ++j) {
            const int col = n0 + wn + j * 8 + tig * 2;
            const size_t a0 = ((size_t)b * Ci + r) * NSP + col;
            const size_t a1 = ((size_t)b * Ci + r + 8) * NSP + col;
            unsigned short h0, l0, h1, l1;
            split1(acc[i][j][0], h0, l0); split1(acc[i][j][1], h1, l1);
            *(unsigned*)(y_h + a0) = pack2(h0, h1); *(unsigned*)(y_l + a0) = pack2(l0, l1);
            split1(acc[i][j][2], h0, l0); split1(acc[i][j][3], h1, l1);
            *(unsigned*)(y_h + a1) = pack2(h0, h1); *(unsigned*)(y_l + a1) = pack2(l0, l1);
        }
    }
}

// ---------------------------------------------------------------------------
// Kernel 5: final. A = Ww natural; B = y k-major. 4 warps, 64x64, NO unroll.
// ---------------------------------------------------------------------------
__global__ __launch_bounds__(TPB4, 2)
void k_final(const float* __restrict__ Wb, const float* __restrict__ gamma,
             const float* __restrict__ beta, const float* __restrict__ mean,
             const float* __restrict__ var, const float* __restrict__ x,
             float* __restrict__ out)
{
    extern __shared__ char smdyn[];
    const unsigned sb = smaddr(smdyn);
    const int tid = threadIdx.x, lane = tid & 31, wid = tid >> 5;
    const int wm = (wid >> 1) * 64, wn = (wid & 1) * 64;
    const int n0 = blockIdx.x * 128, c0 = blockIdx.y * 128, b = blockIdx.z;

    const unsigned short* Ah = ww_h + (size_t)c0 * Ci;
    const unsigned short* Al = ww_l + (size_t)c0 * Ci;
    const unsigned short* Yh = y_h + (size_t)b * Ci * NSP;
    const unsigned short* Yl = y_l + (size_t)b * Ci * NSP;

    const int row = tid >> 2, q = tid & 3;
    const unsigned short* nsrc = (q < 2 ? Ah : Al) + (size_t)row * Ci + (q & 1) * 8;
    const unsigned nd = (unsigned)((row * ANS2 + (q >> 1) * 16 + (q & 1) * 8) * 2);
    const size_t n32 = (size_t)32 * Ci;
    const int k0 = tid >> 4, c8 = tid & 15;
    const unsigned short* ksH = Yh + (size_t)k0 * NSP + n0 + c8 * 8;
    const unsigned short* ksL = Yl + (size_t)k0 * NSP + n0 + c8 * 8;
    const unsigned kd = (unsigned)((k0 * KMS + c8 * 8) * 2) + NAT_B;
    const size_t k8 = (size_t)8 * NSP;
    const size_t kadv = (size_t)16 * NSP;

#define ISSUE_F(s) { const unsigned base = sb + (s) * SOFF_PROJ;                    \
        cpa16s(base + nd, nsrc);                      cpa16s(base + nd + NAT_STEP, nsrc + n32); \
        cpa16s(base + nd + 2 * NAT_STEP, nsrc + 2 * n32); cpa16s(base + nd + 3 * NAT_STEP, nsrc + 3 * n32); \
        cpa16s(base + kd, ksH);            cpa16s(base + kd + KM8, ksH + k8);       \
        cpa16s(base + kd + KM_PLANE, ksL); cpa16s(base + kd + KM_PLANE + KM8, ksL + k8); \
        cp_commit(); nsrc += 16; ksH += kadv; ksL += kadv; }

    unsigned aofs[4], bofs[4];
    mk_aofs_nat(lane, wm, aofs);
    mk_bofs_kmt<4>(lane, wn, bofs);

    ISSUE_F(0) ISSUE_F(1) ISSUE_F(2)
    ACC_INIT(acc, 8);
    const int KT = Ci / 16;
    for (int kt = 0; kt < KT; ++kt) {
        PIPE_WAIT(kt, KT);
        __syncthreads();
        if (kt + 3 < KT) ISSUE_F((kt + 3) & 3)
        const unsigned base = sb + (kt & 3) * SOFF_PROJ;
        comp_tile<4, false, true>(base, base + NAT_B, aofs, bofs, acc);
    }
#undef ISSUE_F

    const int gid = lane >> 2, tig = lane & 3;
    #pragma unroll
    for (int i = 0; i < 4; ++i) {
        const int ch0 = c0 + wm + i * 16 + gid;
        const int ch1 = ch0 + 8;
        const float sg0 = rsqrtf(var[ch0] + 1e-5f) * gamma[ch0];
        const float of0 = (Wb[ch0] - mean[ch0]) * sg0 + beta[ch0];
        const float sg1 = rsqrtf(var[ch1] + 1e-5f) * gamma[ch1];
        const float of1 = (Wb[ch1] - mean[ch1]) * sg1 + beta[ch1];
        #pragma unroll
        for (int j = 0; j < 8; ++j) {
            const int col = n0 + wn + j * 8 + tig * 2;
            const size_t p0 = ((size_t)b * C + ch0) * NSP + col;
            const size_t p1 = ((size_t)b * C + ch1) * NSP + col;
            const float2 x0 = *(const float2*)(x + p0);
            const float2 x1 = *(const float2*)(x + p1);
            float2 o0 = { acc[i][j][0] * sg0 + of0 + x0.x,
                          acc[i][j][1] * sg0 + of0 + x0.y };
            float2 o1 = { acc[i][j][2] * sg1 + of1 + x1.x,
                          acc[i][j][3] * sg1 + of1 + x1.y };
            *(float2*)(out + p0) = o0;
            *(float2*)(out + p1) = o1;
        }
    }
}

// ---------------------------------------------------------------------------
extern "C" void kernel_launch(void* const* d_in, const int* in_sizes, int n_in,
                              void* d_out, int out_size)
{
    const float* x     = (const float*)d_in[0];
    const float* g_w   = (const float*)d_in[1];
    const float* g_b   = (const float*)d_in[2];
    const float* th_w  = (const float*)d_in[3];
    const float* th_b  = (const float*)d_in[4];
    const float* ph_w  = (const float*)d_in[5];
    const float* ph_b  = (const float*)d_in[6];
    const float* W_w   = (const float*)d_in[7];
    const float* W_b   = (const float*)d_in[8];
    const float* gamma = (const float*)d_in[9];
    const float* beta  = (const float*)d_in[10];
    const float* mean  = (const float*)d_in[11];
    const float* var   = (const float*)d_in[12];
    float* out = (float*)d_out;

    cudaFuncSetAttribute(k_proj,   cudaFuncAttributeMaxDynamicSharedMemorySize, SM_PROJ);
    cudaFuncSetAttribute(k_scores, cudaFuncAttributeMaxDynamicSharedMemorySize, SM_SCORE);
    cudaFuncSetAttribute(k_ygemm,  cudaFuncAttributeMaxDynamicSharedMemorySize, SM_YG);
    cudaFuncSetAttribute(k_final,  cudaFuncAttributeMaxDynamicSharedMemorySize, SM_PROJ);

    k_prep_w <<<(1536 * 1024 + 1024 * 512 + 255) / 256, 256>>>(g_w, th_w, ph_w, W_w);
    k_prep_x <<<(int)(((size_t)Bn * C * NSP) / 512), 256>>>(x);
    k_proj   <<<dim3(NSP / 128, 12, Bn), TPB4, SM_PROJ>>>(g_b, th_b, ph_b);
    k_scores <<<dim3(NSP / 128, NSP / 128, Bn), TPB8, SM_SCORE>>>();
    k_softmax<<<dim3(Bn * NSP), SOFT_TPB>>>();
    k_ygemm  <<<dim3(NSP / 128, Ci / 128, Bn), TPB4, SM_YG>>>();
    k_final  <<<dim3(NSP / 128, C / 128, Bn), TPB4, SM_PROJ>>>(W_b, gamma, beta, mean, var, x, out);
}

// round 14
// speedup vs baseline: 1.0608x; 1.0608x over previous
#include <cuda_runtime.h>
#include <cuda_bf16.h>
#include <cstddef>
#include <cstdint>

// B=8, C=1024, Ci=512, N=T*H*W=2048
constexpr int Bn   = 8;
constexpr int C    = 1024;
constexpr int Ci   = 512;
constexpr int NSP  = 2048;

constexpr int TPB4     = 128;   // 4 warps, warp tile 64x64 (proj/ygemm/final)
constexpr int TPB8     = 256;   // 8 warps, warp tile 64x32 (scores)
constexpr int SOFT_TPB = 256;

// smem tile geometry (bf16 elements)
constexpr int ANS2     = 40;             // natural combined hi|lo row stride
constexpr int NAT_B    = 128 * ANS2 * 2; // 10240 bytes per natural tile
constexpr int NAT_STEP = 32 * ANS2 * 2;  // row+32 dst step
constexpr int KMS      = 136;            // k-major plane row stride
constexpr int KM_PLANE = 16 * KMS * 2;   // 4352 bytes per plane
constexpr int KM_B     = 2 * KM_PLANE;   // 8704 bytes (hi+lo)
constexpr int KM8      = 8 * KMS * 2;    // k+8 dst step

// stage strides / total dynamic smem
constexpr int SOFF_PROJ  = NAT_B + KM_B;   // 18944
constexpr int SOFF_SCORE = KM_B + KM_B;    // 17408
constexpr int SOFF_YG    = NAT_B + NAT_B;  // 20480
constexpr int SM_PROJ  = 4 * SOFF_PROJ;
constexpr int SM_SCORE = 4 * SOFF_SCORE;
constexpr int SM_YG    = 4 * SOFF_YG;

// ---------------------------------------------------------------------------
// gmem scratch
// ---------------------------------------------------------------------------
__device__ float d_f[(size_t)Bn * NSP * NSP];
__device__ __align__(16) unsigned short x_h[(size_t)Bn * C * NSP],  x_l[(size_t)Bn * C * NSP];
__device__ __align__(16) unsigned short w3_h[1536 * 1024],          w3_l[1536 * 1024];
__device__ __align__(16) unsigned short ww_h[1024 * 512],           ww_l[1024 * 512];
__device__ __align__(16) unsigned short g_h[(size_t)Bn * Ci * NSP], g_l[(size_t)Bn * Ci * NSP];
__device__ __align__(16) unsigned short th_h[(size_t)Bn * Ci * NSP], th_l[(size_t)Bn * Ci * NSP];
__device__ __align__(16) unsigned short ph_h[(size_t)Bn * Ci * NSP], ph_l[(size_t)Bn * Ci * NSP];
__device__ __align__(16) unsigned short P_h[(size_t)Bn * NSP * NSP], P_l[(size_t)Bn * NSP * NSP];
__device__ __align__(16) unsigned short y_h[(size_t)Bn * Ci * NSP],  y_l[(size_t)Bn * Ci * NSP];

// ---------------------------------------------------------------------------
// helpers
// ---------------------------------------------------------------------------
__device__ __forceinline__ unsigned smaddr(const void* p) {
    return (unsigned)__cvta_generic_to_shared(p);
}
__device__ __forceinline__ void cpa16s(unsigned daddr, const void* src) {
    asm volatile("cp.async.cg.shared.global [%0], [%1], 16;"
                 :: "r"(daddr), "l"(src) : "memory");
}
__device__ __forceinline__ void cp_commit() { asm volatile("cp.async.commit_group;" ::: "memory"); }
template<int N> __device__ __forceinline__ void cp_wait() {
    asm volatile("cp.async.wait_group %0;" :: "n"(N) : "memory");
}
__device__ __forceinline__ void ldsm4a(unsigned addr, unsigned& r0, unsigned& r1,
                                       unsigned& r2, unsigned& r3) {
    asm volatile("ldmatrix.sync.aligned.m8n8.x4.shared.b16 {%0,%1,%2,%3}, [%4];"
                 : "=r"(r0), "=r"(r1), "=r"(r2), "=r"(r3) : "r"(addr));
}
__device__ __forceinline__ void ldsm4ta(unsigned addr, unsigned& r0, unsigned& r1,
                                        unsigned& r2, unsigned& r3) {
    asm volatile("ldmatrix.sync.aligned.m8n8.x4.trans.shared.b16 {%0,%1,%2,%3}, [%4];"
                 : "=r"(r0), "=r"(r1), "=r"(r2), "=r"(r3) : "r"(addr));
}
__device__ __forceinline__ void mma_bf(float* c, const unsigned* a, unsigned b0, unsigned b1) {
    asm volatile(
        "mma.sync.aligned.m16n8k16.row.col.f32.bf16.bf16.f32 "
        "{%0,%1,%2,%3}, {%4,%5,%6,%7}, {%8,%9}, {%0,%1,%2,%3};"
        : "+f"(c[0]), "+f"(c[1]), "+f"(c[2]), "+f"(c[3])
        : "r"(a[0]), "r"(a[1]), "r"(a[2]), "r"(a[3]), "r"(b0), "r"(b1));
}
__device__ __forceinline__ void split1(float v, unsigned short& h, unsigned short& l) {
    __nv_bfloat16 hb = __float2bfloat16_rn(v);
    __nv_bfloat16 lb = __float2bfloat16_rn(v - __bfloat162float(hb));
    h = *reinterpret_cast<unsigned short*>(&hb);
    l = *reinterpret_cast<unsigned short*>(&lb);
}
__device__ __forceinline__ unsigned pack2(unsigned short a, unsigned short b) {
    return (unsigned)a | ((unsigned)b << 16);
}

// fragment offset builders (byte offsets within a stage's operand tile)
__device__ __forceinline__ void mk_aofs_nat(int lane, int wm, unsigned* o) {
    #pragma unroll
    for (int i = 0; i < 4; ++i)
        o[i] = (unsigned)(((wm + i * 16 + (lane & 15)) * ANS2 + ((lane >> 4) & 1) * 8) * 2);
}
__device__ __forceinline__ void mk_aofs_kmt(int lane, int wm, unsigned* o) {
    const int k = (lane & 7) + ((lane >> 3) & 1) * 8;
    #pragma unroll
    for (int i = 0; i < 4; ++i)
        o[i] = (unsigned)((k * KMS + wm + i * 16 + (lane >> 4) * 8) * 2);
}
template<int JT>
__device__ __forceinline__ void mk_bofs_kmt(int lane, int wn, unsigned* o) {
    const int k = (lane & 7) + ((lane >> 3) & 1) * 8;
    #pragma unroll
    for (int jj = 0; jj < JT; ++jj)
        o[jj] = (unsigned)((k * KMS + wn + jj * 16 + (lane >> 4) * 8) * 2);
}
template<int JT>
__device__ __forceinline__ void mk_bofs_nat(int lane, int wn, unsigned* o) {
    #pragma unroll
    for (int jj = 0; jj < JT; ++jj)
        o[jj] = (unsigned)(((wn + jj * 16 + ((lane >> 4) & 1) * 8 + (lane & 7)) * ANS2
                            + ((lane >> 3) & 1) * 8) * 2);
}

// A fragment loader (one i-tile, hi+lo)
template<bool AKM>
__device__ __forceinline__ void load_a(unsigned ab, unsigned aof,
                                       unsigned* ah, unsigned* al) {
    if (AKM) {
        unsigned r0, r1, r2, r3;
        ldsm4ta(ab + aof, r0, r1, r2, r3);
        ah[0] = r0; ah[1] = r2; ah[2] = r1; ah[3] = r3;
        ldsm4ta(ab + KM_PLANE + aof, r0, r1, r2, r3);
        al[0] = r0; al[1] = r2; al[2] = r1; al[3] = r3;
    } else {
        ldsm4a(ab + aof,      ah[0], ah[1], ah[2], ah[3]);
        ldsm4a(ab + aof + 32, al[0], al[1], al[2], al[3]);
    }
}

// 3xBF16 warp-tile compute for one k16 stage. JT = n16-tiles per warp (2 or 4).
// Software-pipelined: all B fragments loaded up front; A fragments double-
// buffered so each A ldsm pair hides under the previous i-tile's MMA batch.
// Per-accumulator term order (hh, hl, lh) unchanged -> bit-identical results.
template<int JT, bool AKM, bool BKM>
__device__ __forceinline__ void comp_tile(unsigned ab, unsigned bb,
                                          const unsigned* aofs, const unsigned* bofs,
                                          float (&acc)[4][2 * JT][4]) {
    unsigned bh[JT][4], bl[JT][4];
    #pragma unroll
    for (int jj = 0; jj < JT; ++jj) {
        if (BKM) {
            ldsm4ta(bb + bofs[jj],            bh[jj][0], bh[jj][1], bh[jj][2], bh[jj][3]);
            ldsm4ta(bb + KM_PLANE + bofs[jj], bl[jj][0], bl[jj][1], bl[jj][2], bl[jj][3]);
        } else {
            ldsm4a(bb + bofs[jj],      bh[jj][0], bh[jj][1], bh[jj][2], bh[jj][3]);
            ldsm4a(bb + bofs[jj] + 32, bl[jj][0], bl[jj][1], bl[jj][2], bl[jj][3]);
        }
    }
    unsigned ah[2][4], al[2][4];
    load_a<AKM>(ab, aofs[0], ah[0], al[0]);
    #pragma unroll
    for (int i = 0; i < 4; ++i) {
        const int cur = i & 1, nxt = cur ^ 1;
        if (i < 3) load_a<AKM>(ab, aofs[i + 1], ah[nxt], al[nxt]);
        #pragma unroll
        for (int jj = 0; jj < JT; ++jj)
            #pragma unroll
            for (int jr = 0; jr < 2; ++jr)
                mma_bf(acc[i][jj * 2 + jr], ah[cur], bh[jj][jr*2], bh[jj][jr*2+1]);
        #pragma unroll
        for (int jj = 0; jj < JT; ++jj)
            #pragma unroll
            for (int jr = 0; jr < 2; ++jr)
                mma_bf(acc[i][jj * 2 + jr], ah[cur], bl[jj][jr*2], bl[jj][jr*2+1]);
        #pragma unroll
        for (int jj = 0; jj < JT; ++jj)
            #pragma unroll
            for (int jr = 0; jr < 2; ++jr)
                mma_bf(acc[i][jj * 2 + jr], al[cur], bh[jj][jr*2], bh[jj][jr*2+1]);
    }
}

#define ACC_INIT(acc, JN)                                    \
    float acc[4][JN][4];                                     \
    _Pragma("unroll") for (int i = 0; i < 4; ++i)            \
    _Pragma("unroll") for (int j = 0; j < JN; ++j)           \
    _Pragma("unroll") for (int q = 0; q < 4; ++q) acc[i][j][q] = 0.f;

#define PIPE_WAIT(kt, KT)                                    \
    if ((kt) + 2 < (KT)) cp_wait<2>();                       \
    else if ((kt) + 1 < (KT)) cp_wait<1>();                  \
    else cp_wait<0>();

// ---------------------------------------------------------------------------
// Pre-pass
// ---------------------------------------------------------------------------
__global__ void k_prep_w(const float* __restrict__ gw, const float* __restrict__ tw,
                         const float* __restrict__ pw, const float* __restrict__ Ww)
{
    const int idx = blockIdx.x * 256 + threadIdx.x;
    if (idx < 1536 * 1024) {
        const int r = idx >> 10, c = idx & 1023;
        float v = (r < 512) ? gw[r * 1024 + c]
                 : (r < 1024) ? tw[(r - 512) * 1024 + c]
                 : pw[(r - 1024) * 1024 + c];
        split1(v, w3_h[idx], w3_l[idx]);
    } else if (idx < 1536 * 1024 + 1024 * 512) {
        const int j = idx - 1536 * 1024;
        split1(Ww[j], ww_h[j], ww_l[j]);
    }
}
__global__ void k_prep_x(const float* __restrict__ x)
{
    const size_t i0 = ((size_t)blockIdx.x * 256 + threadIdx.x) * 2;
    const float2 v = *(const float2*)(x + i0);
    unsigned short h0, l0, h1, l1;
    split1(v.x, h0, l0); split1(v.y, h1, l1);
    *(unsigned*)(x_h + i0) = pack2(h0, h1);
    *(unsigned*)(x_l + i0) = pack2(l0, l1);
}

// ---------------------------------------------------------------------------
// Kernel 1: projections. A = W3 natural [o][c]; B = x k-major [c][n].
// 4 warps, 64x64 warp tile.
// ---------------------------------------------------------------------------
__global__ __launch_bounds__(TPB4, 2)
void k_proj(const float* __restrict__ gb, const float* __restrict__ tbias,
            const float* __restrict__ pb)
{
    extern __shared__ char smdyn[];
    const unsigned sb = smaddr(smdyn);
    const int tid = threadIdx.x, lane = tid & 31, wid = tid >> 5;
    const int wm = (wid >> 1) * 64, wn = (wid & 1) * 64;
    const int n0 = blockIdx.x * 128, mt = blockIdx.y, b = blockIdx.z;
    const int mloc = (mt & 3) * 128;

    const unsigned short* Ah = w3_h + (size_t)mt * 128 * 1024;
    const unsigned short* Al = w3_l + (size_t)mt * 128 * 1024;
    const unsigned short* Xh = x_h + (size_t)b * C * NSP;
    const unsigned short* Xl = x_l + (size_t)b * C * NSP;

    const int row = tid >> 2, q = tid & 3;
    const unsigned short* nsrc = (q < 2 ? Ah : Al) + (size_t)row * 1024 + (q & 1) * 8;
    const unsigned nd = (unsigned)((row * ANS2 + (q >> 1) * 16 + (q & 1) * 8) * 2);
    const size_t n32 = (size_t)32 * 1024;
    const int k0 = tid >> 4, c8 = tid & 15;
    const unsigned short* ksH = Xh + (size_t)k0 * NSP + n0 + c8 * 8;
    const unsigned short* ksL = Xl + (size_t)k0 * NSP + n0 + c8 * 8;
    const unsigned kd = (unsigned)((k0 * KMS + c8 * 8) * 2) + NAT_B;
    const size_t k8 = (size_t)8 * NSP;
    const size_t kadv = (size_t)16 * NSP;

#define ISSUE_P(s) { const unsigned base = sb + (s) * SOFF_PROJ;                    \
        cpa16s(base + nd, nsrc);                      cpa16s(base + nd + NAT_STEP, nsrc + n32); \
        cpa16s(base + nd + 2 * NAT_STEP, nsrc + 2 * n32); cpa16s(base + nd + 3 * NAT_STEP, nsrc + 3 * n32); \
        cpa16s(base + kd, ksH);            cpa16s(base + kd + KM8, ksH + k8);       \
        cpa16s(base + kd + KM_PLANE, ksL); cpa16s(base + kd + KM_PLANE + KM8, ksL + k8); \
        cp_commit(); nsrc += 16; ksH += kadv; ksL += kadv; }

    unsigned aofs[4], bofs[4];
    mk_aofs_nat(lane, wm, aofs);
    mk_bofs_kmt<4>(lane, wn, bofs);

    ISSUE_P(0) ISSUE_P(1) ISSUE_P(2)
    ACC_INIT(acc, 8);
    const int KT = C / 16;
    for (int kt = 0; kt < KT; ++kt) {
        PIPE_WAIT(kt, KT);
        __syncthreads();
        const unsigned base = sb + (kt & 3) * SOFF_PROJ;
        comp_tile<4, false, true>(base, base + NAT_B, aofs, bofs, acc);
        if (kt + 3 < KT) ISSUE_P((kt + 3) & 3)
    }
#undef ISSUE_P

    const int gid = lane >> 2, tig = lane & 3;
    unsigned short *H, *L;
    const float* bias;
    if (mt < 4)      { H = g_h;  L = g_l;  bias = gb; }
    else if (mt < 8) { H = th_h; L = th_l; bias = tbias; }
    else             { H = ph_h; L = ph_l; bias = pb; }

    #pragma unroll
    for (int i = 0; i < 4; ++i) {
        const int ol = mloc + wm + i * 16 + gid;
        const float bv0 = bias[ol], bv1 = bias[ol + 8];
        #pragma unroll
        for (int j = 0; j < 8; ++j) {
            const int col = n0 + wn + j * 8 + tig * 2;
            const size_t a0 = ((size_t)b * Ci + ol) * NSP + col;
            const size_t a1 = ((size_t)b * Ci + ol + 8) * NSP + col;
            unsigned short h0, l0, h1, l1;
            split1(acc[i][j][0] + bv0, h0, l0); split1(acc[i][j][1] + bv0, h1, l1);
            *(unsigned*)(H + a0) = pack2(h0, h1); *(unsigned*)(L + a0) = pack2(l0, l1);
            split1(acc[i][j][2] + bv1, h0, l0); split1(acc[i][j][3] + bv1, h1, l1);
            *(unsigned*)(H + a1) = pack2(h0, h1); *(unsigned*)(L + a1) = pack2(l0, l1);
        }
    }
}

// ---------------------------------------------------------------------------
// Kernel 2: scores. Both operands k-major. 8 warps, 64x32 warp tile, unroll 4.
// ---------------------------------------------------------------------------
__global__ __launch_bounds__(TPB8, 2)
void k_scores()
{
    extern __shared__ char smdyn[];
    const unsigned sb = smaddr(smdyn);
    const int tid = threadIdx.x, lane = tid & 31, wid = tid >> 5;
    const int wm = (wid >> 2) * 64, wn = (wid & 3) * 32;
    const int m0 = blockIdx.x * 128, r0 = blockIdx.y * 128, b = blockIdx.z;

    const unsigned short* Th = th_h + (size_t)b * Ci * NSP;
    const unsigned short* Tl = th_l + (size_t)b * Ci * NSP;
    const unsigned short* Ph = ph_h + (size_t)b * Ci * NSP;
    const unsigned short* Pl = ph_l + (size_t)b * Ci * NSP;

    const int k0 = tid >> 4, c8 = tid & 15;
    const size_t kadv = (size_t)16 * NSP;
    const unsigned short* aH = Th + (size_t)k0 * NSP + r0 + c8 * 8;
    const unsigned short* aL = Tl + (size_t)k0 * NSP + r0 + c8 * 8;
    const unsigned short* bH = Ph + (size_t)k0 * NSP + m0 + c8 * 8;
    const unsigned short* bL = Pl + (size_t)k0 * NSP + m0 + c8 * 8;
    const unsigned ad = (unsigned)((k0 * KMS + c8 * 8) * 2);
    const unsigned bd = ad + KM_B;

#define ISSUE_S(s) { const unsigned base = sb + (s) * SOFF_SCORE;                   \
        cpa16s(base + ad, aH); cpa16s(base + ad + KM_PLANE, aL);                    \
        cpa16s(base + bd, bH); cpa16s(base + bd + KM_PLANE, bL);                    \
        cp_commit(); aH += kadv; aL += kadv; bH += kadv; bL += kadv; }

    unsigned aofs[4], bofs[2];
    mk_aofs_kmt(lane, wm, aofs);
    mk_bofs_kmt<2>(lane, wn, bofs);

    ISSUE_S(0) ISSUE_S(1) ISSUE_S(2)
    ACC_INIT(acc, 4);
    const int KT = Ci / 16;
    #pragma unroll 4
    for (int kt = 0; kt < KT; ++kt) {
        PIPE_WAIT(kt, KT);
        __syncthreads();
        const unsigned base = sb + (kt & 3) * SOFF_SCORE;
        comp_tile<2, true, true>(base, base + KM_B, aofs, bofs, acc);
        if (kt + 3 < KT) ISSUE_S((kt + 3) & 3)
    }
#undef ISSUE_S

    const int gid = lane >> 2, tig = lane & 3;
    float* fb = d_f + (size_t)b * NSP * NSP;
    #pragma unroll
    for (int i = 0; i < 4; ++i) {
        const int r = r0 + wm + i * 16 + gid;
        #pragma unroll
        for (int j = 0; j < 4; ++j) {
            const int col = m0 + wn + j * 8 + tig * 2;
            *(float2*)(fb + (size_t)r * NSP + col)       = *(float2*)&acc[i][j][0];
            *(float2*)(fb + (size_t)(r + 8) * NSP + col) = *(float2*)&acc[i][j][2];
        }
    }
}

// ---------------------------------------------------------------------------
// Kernel 3: softmax rows of d_f -> P hi/lo planes
// ---------------------------------------------------------------------------
__global__ __launch_bounds__(SOFT_TPB)
void k_softmax()
{
    const int tid = threadIdx.x;
    const size_t rowi = blockIdx.x;
    const float* row = d_f + rowi * NSP;

    float v[8];
    *(float4*)&v[0] = *(const float4*)(row + tid * 8);
    *(float4*)&v[4] = *(const float4*)(row + tid * 8 + 4);

    float m = v[0];
    #pragma unroll
    for (int i = 1; i < 8; i++) m = fmaxf(m, v[i]);
    #pragma unroll
    for (int o = 16; o; o >>= 1) m = fmaxf(m, __shfl_xor_sync(0xffffffffu, m, o));

    __shared__ float redm[8], reds[8];
    const int wid = tid >> 5, lane = tid & 31;
    if (lane == 0) redm[wid] = m;
    __syncthreads();
    m = redm[0];
    #pragma unroll
    for (int i = 1; i < 8; i++) m = fmaxf(m, redm[i]);

    float s = 0.f;
    #pragma unroll
    for (int i = 0; i < 8; i++) { v[i] = __expf(v[i] - m); s += v[i]; }
    #pragma unroll
    for (int o = 16; o; o >>= 1) s += __shfl_xor_sync(0xffffffffu, s, o);
    if (lane == 0) reds[wid] = s;
    __syncthreads();
    s = reds[0];
    #pragma unroll
    for (int i = 1; i < 8; i++) s += reds[i];

    const float inv = 1.0f / s;
    unsigned* Hp = (unsigned*)(P_h + rowi * NSP + tid * 8);
    unsigned* Lp = (unsigned*)(P_l + rowi * NSP + tid * 8);
    #pragma unroll
    for (int p = 0; p < 4; ++p) {
        unsigned short h0, l0, h1, l1;
        split1(v[2*p] * inv, h0, l0); split1(v[2*p+1] * inv, h1, l1);
        Hp[p] = pack2(h0, h1); Lp[p] = pack2(l0, l1);
    }
}

// ---------------------------------------------------------------------------
// Kernel 4: ygemm. Both operands natural. 4 warps, 64x64.
// ---------------------------------------------------------------------------
__global__ __launch_bounds__(TPB4, 2)
void k_ygemm()
{
    extern __shared__ char smdyn[];
    const unsigned sb = smaddr(smdyn);
    const int tid = threadIdx.x, lane = tid & 31, wid = tid >> 5;
    const int wm = (wid >> 1) * 64, wn = (wid & 1) * 64;
    const int n0 = blockIdx.x * 128, c0 = blockIdx.y * 128, b = blockIdx.z;

    const unsigned short* Gh = g_h + ((size_t)b * Ci + c0) * NSP;
    const unsigned short* Gl = g_l + ((size_t)b * Ci + c0) * NSP;
    const unsigned short* Qh = P_h + ((size_t)b * NSP + n0) * NSP;
    const unsigned short* Ql = P_l + ((size_t)b * NSP + n0) * NSP;

    const int row = tid >> 2, q = tid & 3;
    const size_t roff = (size_t)row * NSP + (q & 1) * 8;
    const unsigned short* asrc = (q < 2 ? Gh : Gl) + roff;
    const unsigned short* bsrc = (q < 2 ? Qh : Ql) + roff;
    const unsigned nd = (unsigned)((row * ANS2 + (q >> 1) * 16 + (q & 1) * 8) * 2);
    const size_t n32 = (size_t)32 * NSP;

#define ISSUE_Y(s) { const unsigned base = sb + (s) * SOFF_YG;                      \
        cpa16s(base + nd, asrc);                        cpa16s(base + nd + NAT_STEP, asrc + n32); \
        cpa16s(base + nd + 2 * NAT_STEP, asrc + 2 * n32); cpa16s(base + nd + 3 * NAT_STEP, asrc + 3 * n32); \
        cpa16s(base + NAT_B + nd, bsrc);                cpa16s(base + NAT_B + nd + NAT_STEP, bsrc + n32); \
        cpa16s(base + NAT_B + nd + 2 * NAT_STEP, bsrc + 2 * n32); \
        cpa16s(base + NAT_B + nd + 3 * NAT_STEP, bsrc + 3 * n32); \
        cp_commit(); asrc += 16; bsrc += 16; }

    unsigned aofs[4], bofs[4];
    mk_aofs_nat(lane, wm, aofs);
    mk_bofs_nat<4>(lane, wn, bofs);

    ISSUE_Y(0) ISSUE_Y(1) ISSUE_Y(2)
    ACC_INIT(acc, 8);
    const int KT = NSP / 16;
    for (int kt = 0; kt < KT; ++kt) {
        PIPE_WAIT(kt, KT);
        __syncthreads();
        const unsigned base = sb + (kt & 3) * SOFF_YG;
        comp_tile<4, false, false>(base, base + NAT_B, aofs, bofs, acc);
        if (kt + 3 < KT) ISSUE_Y((kt + 3) & 3)
    }
#undef ISSUE_Y

    const int gid = lane >> 2, tig = lane & 3;
    #pragma unroll
    for (int i = 0; i < 4; ++i) {
        const int r = c0 + wm + i * 16 + gid;
        #pragma unroll
        for (int j = 0; j < 8; ++j) {
            const int col = n0 + wn + j * 8 + tig * 2;
            const size_t a0 = ((size_t)b * Ci + r) * NSP + col;
            const size_t a1 = ((size_t)b * Ci + r + 8) * NSP + col;
            unsigned short h0, l0, h1, l1;
            split1(acc[i][j][0], h0, l0); split1(acc[i][j][1], h1, l1);
            *(unsigned*)(y_h + a0) = pack2(h0, h1); *(unsigned*)(y_l + a0) = pack2(l0, l1);
            split1(acc[i][j][2], h0, l0); split1(acc[i][j][3], h1, l1);
            *(unsigned*)(y_h + a1) = pack2(h0, h1); *(unsigned*)(y_l + a1) = pack2(l0, l1);
        }
    }
}

// ---------------------------------------------------------------------------
// Kernel 5: final. A = Ww natural; B = y k-major. 4 warps, 64x64.
// ---------------------------------------------------------------------------
__global__ __launch_bounds__(TPB4, 2)
void k_final(const float* __restrict__ Wb, const float* __restrict__ gamma,
             const float* __restrict__ beta, const float* __restrict__ mean,
             const float* __restrict__ var, const float* __restrict__ x,
             float* __restrict__ out)
{
    extern __shared__ char smdyn[];
    const unsigned sb = smaddr(smdyn);
    const int tid = threadIdx.x, lane = tid & 31, wid = tid >> 5;
    const int wm = (wid >> 1) * 64, wn = (wid & 1) * 64;
    const int n0 = blockIdx.x * 128, c0 = blockIdx.y * 128, b = blockIdx.z;

    const unsigned short* Ah = ww_h + (size_t)c0 * Ci;
    const unsigned short* Al = ww_l + (size_t)c0 * Ci;
    const unsigned short* Yh = y_h + (size_t)b * Ci * NSP;
    const unsigned short* Yl = y_l + (size_t)b * Ci * NSP;

    const int row = tid >> 2, q = tid & 3;
    const unsigned short* nsrc = (q < 2 ? Ah : Al) + (size_t)row * Ci + (q & 1) * 8;
    const unsigned nd = (unsigned)((row * ANS2 + (q >> 1) * 16 + (q & 1) * 8) * 2);
    const size_t n32 = (size_t)32 * Ci;
    const int k0 = tid >> 4, c8 = tid & 15;
    const unsigned short* ksH = Yh + (size_t)k0 * NSP + n0 + c8 * 8;
    const unsigned short* ksL = Yl + (size_t)k0 * NSP + n0 + c8 * 8;
    const unsigned kd = (unsigned)((k0 * KMS + c8 * 8) * 2) + NAT_B;
    const size_t k8 = (size_t)8 * NSP;
    const size_t kadv = (size_t)16 * NSP;

#define ISSUE_F(s) { const unsigned base = sb + (s) * SOFF_PROJ;                    \
        cpa16s(base + nd, nsrc);                      cpa16s(base + nd + NAT_STEP, nsrc + n32); \
        cpa16s(base + nd + 2 * NAT_STEP, nsrc + 2 * n32); cpa16s(base + nd + 3 * NAT_STEP, nsrc + 3 * n32); \
        cpa16s(base + kd, ksH);            cpa16s(base + kd + KM8, ksH + k8);       \
        cpa16s(base + kd + KM_PLANE, ksL); cpa16s(base + kd + KM_PLANE + KM8, ksL + k8); \
        cp_commit(); nsrc += 16; ksH += kadv; ksL += kadv; }

    unsigned aofs[4], bofs[4];
    mk_aofs_nat(lane, wm, aofs);
    mk_bofs_kmt<4>(lane, wn, bofs);

    ISSUE_F(0) ISSUE_F(1) ISSUE_F(2)
    ACC_INIT(acc, 8);
    const int KT = Ci / 16;
    for (int kt = 0; kt < KT; ++kt) {
        PIPE_WAIT(kt, KT);
        __syncthreads();
        const unsigned base = sb + (kt & 3) * SOFF_PROJ;
        comp_tile<4, false, true>(base, base + NAT_B, aofs, bofs, acc);
        if (kt + 3 < KT) ISSUE_F((kt + 3) & 3)
    }
#undef ISSUE_F

    const int gid = lane >> 2, tig = lane & 3;
    #pragma unroll
    for (int i = 0; i < 4; ++i) {
        const int ch0 = c0 + wm + i * 16 + gid;
        const int ch1 = ch0 + 8;
        const float sg0 = rsqrtf(var[ch0] + 1e-5f) * gamma[ch0];
        const float of0 = (Wb[ch0] - mean[ch0]) * sg0 + beta[ch0];
        const float sg1 = rsqrtf(var[ch1] + 1e-5f) * gamma[ch1];
        const float of1 = (Wb[ch1] - mean[ch1]) * sg1 + beta[ch1];
        #pragma unroll
        for (int j = 0; j < 8; ++j) {
            const int col = n0 + wn + j * 8 + tig * 2;
            const size_t p0 = ((size_t)b * C + ch0) * NSP + col;
            const size_t p1 = ((size_t)b * C + ch1) * NSP + col;
            const float2 x0 = *(const float2*)(x + p0);
            const float2 x1 = *(const float2*)(x + p1);
            float2 o0 = { acc[i][j][0] * sg0 + of0 + x0.x,
                          acc[i][j][1] * sg0 + of0 + x0.y };
            float2 o1 = { acc[i][j][2] * sg1 + of1 + x1.x,
                          acc[i][j][3] * sg1 + of1 + x1.y };
            *(float2*)(out + p0) = o0;
            *(float2*)(out + p1) = o1;
        }
    }
}

// ---------------------------------------------------------------------------
extern "C" void kernel_launch(void* const* d_in, const int* in_sizes, int n_in,
                              void* d_out, int out_size)
{
    const float* x     = (const float*)d_in[0];
    const float* g_w   = (const float*)d_in[1];
    const float* g_b   = (const float*)d_in[2];
    const float* th_w  = (const float*)d_in[3];
    const float* th_b  = (const float*)d_in[4];
    const float* ph_w  = (const float*)d_in[5];
    const float* ph_b  = (const float*)d_in[6];
    const float* W_w   = (const float*)d_in[7];
    const float* W_b   = (const float*)d_in[8];
    const float* gamma = (const float*)d_in[9];
    const float* beta  = (const float*)d_in[10];
    const float* mean  = (const float*)d_in[11];
    const float* var   = (const float*)d_in[12];
    float* out = (float*)d_out;

    cudaFuncSetAttribute(k_proj,   cudaFuncAttributeMaxDynamicSharedMemorySize, SM_PROJ);
    cudaFuncSetAttribute(k_scores, cudaFuncAttributeMaxDynamicSharedMemorySize, SM_SCORE);
    cudaFuncSetAttribute(k_ygemm,  cudaFuncAttributeMaxDynamicSharedMemorySize, SM_YG);
    cudaFuncSetAttribute(k_final,  cudaFuncAttributeMaxDynamicSharedMemorySize, SM_PROJ);

    k_prep_w <<<(1536 * 1024 + 1024 * 512 + 255) / 256, 256>>>(g_w, th_w, ph_w, W_w);
    k_prep_x <<<(int)(((size_t)Bn * C * NSP) / 512), 256>>>(x);
    k_proj   <<<dim3(NSP / 128, 12, Bn), TPB4, SM_PROJ>>>(g_b, th_b, ph_b);
    k_scores <<<dim3(NSP / 128, NSP / 128, Bn), TPB8, SM_SCORE>>>();
    k_softmax<<<dim3(Bn * NSP), SOFT_TPB>>>();
    k_ygemm  <<<dim3(NSP / 128, Ci / 128, Bn), TPB4, SM_YG>>>();
    k_final  <<<dim3(NSP / 128, C / 128, Bn), TPB4, SM_PROJ>>>(W_b, gamma, beta, mean, var, x, out);
}